// round 14
// baseline (speedup 1.0000x reference)
#include <cuda_runtime.h>
#include <cuda_fp16.h>
#include <math.h>
#include <stdint.h>

#define DIM 1024
#define NMAX 32768
#define MAXNORM (1.0f - 1e-5f)
#define MIN_NORM 1e-15f

// ---------------- GEMM tiling (R7/R11-proven config) ----------------
#define BM 128
#define BN 128
#define BKE 32                     // fp16 k elements per stage (64 bytes per row)
#define KITERS (DIM / BKE)         // 32
#define STAGES 4
// per-stage layout: A 8KB | B 8KB
#define ST_A 0
#define ST_B 8192
#define STAGE_BYTES 16384
#define SMEM_BYTES (STAGES * STAGE_BYTES)   // 64KB, 2 CTAs/SM

// ---------------- scratch (device globals) ----------------
__device__ float   g_mx[(size_t)NMAX * DIM];   // fp32 GEMM output
__device__ __half  g_a[(size_t)NMAX * DIM];    // activations fp16
__device__ __half  g_w1[DIM * DIM];
__device__ __half  g_w2[DIM * DIM];
__device__ float   g_xn[NMAX];
__device__ float   g_hb[2][DIM];
__device__ float   g_y2[2];

// ---------------- PTX helpers ----------------
__device__ __forceinline__ uint32_t smem_u32(const void* p) {
    uint32_t a;
    asm("{ .reg .u64 t; cvta.to.shared.u64 t, %1; cvt.u32.u64 %0, t; }" : "=r"(a) : "l"(p));
    return a;
}
#define CP_ASYNC16(dst, src) \
    asm volatile("cp.async.cg.shared.global [%0], [%1], 16;" :: "r"(dst), "l"(src) : "memory")
#define CP_COMMIT() asm volatile("cp.async.commit_group;" ::: "memory")
#define CP_WAIT2()  asm volatile("cp.async.wait_group 2;" ::: "memory")
#define CP_WAIT1()  asm volatile("cp.async.wait_group 1;" ::: "memory")
#define CP_WAIT0()  asm volatile("cp.async.wait_group 0;" ::: "memory")

__device__ __forceinline__ void ldsm4(uint32_t* r, uint32_t addr) {
    asm volatile("ldmatrix.sync.aligned.m8n8.x4.shared.b16 {%0,%1,%2,%3}, [%4];"
                 : "=r"(r[0]), "=r"(r[1]), "=r"(r[2]), "=r"(r[3]) : "r"(addr));
}
__device__ __forceinline__ void mma16816(float* c, const uint32_t* a, uint32_t b0, uint32_t b1) {
    asm volatile("mma.sync.aligned.m16n8k16.row.col.f32.f16.f16.f32 "
                 "{%0,%1,%2,%3}, {%4,%5,%6,%7}, {%8,%9}, {%0,%1,%2,%3};"
                 : "+f"(c[0]), "+f"(c[1]), "+f"(c[2]), "+f"(c[3])
                 : "r"(a[0]), "r"(a[1]), "r"(a[2]), "r"(a[3]), "r"(b0), "r"(b1));
}

// swizzled byte offset: 64B rows, 16B chunks, c in 0..3
__device__ __forceinline__ uint32_t swz64(int row, int c) {
    return (uint32_t)(row * 64 + ((c ^ ((row >> 1) & 3)) * 16));
}

// ---------------- generic helpers ----------------
__device__ __forceinline__ float artanh_clip(float x) {
    const float lim = 1.0f - 1e-7f;
    x = fminf(fmaxf(x, -lim), lim);
    return atanhf(x);
}
__device__ __forceinline__ float blockReduceSum(float v) {
    __shared__ float sbuf[32];
    #pragma unroll
    for (int o = 16; o > 0; o >>= 1) v += __shfl_xor_sync(0xffffffffu, v, o);
    const int lane = threadIdx.x & 31;
    const int w    = threadIdx.x >> 5;
    if (lane == 0) sbuf[w] = v;
    __syncthreads();
    if (w == 0) {
        float t = (lane < 8) ? sbuf[lane] : 0.0f;
        #pragma unroll
        for (int o = 4; o > 0; o >>= 1) t += __shfl_xor_sync(0xffffffffu, t, o);
        if (lane == 0) sbuf[0] = t;
    }
    __syncthreads();
    float r = sbuf[0];
    __syncthreads();
    return r;
}

// ---------------- small kernels (merged prologue) ----------------
__global__ __launch_bounds__(256)
void cvtw2_kernel(const float* __restrict__ W1, __half* __restrict__ H1,
                  const float* __restrict__ W2, __half* __restrict__ H2,
                  int nblk) {
    const bool second = (blockIdx.x >= nblk);
    const float* W = second ? W2 : W1;
    __half* H      = second ? H2 : H1;
    const size_t i = (size_t)(second ? blockIdx.x - nblk : blockIdx.x) * 256 + threadIdx.x;
    float4 v = reinterpret_cast<const float4*>(W)[i];
    __half2 a, b;
    a.x = __float2half(v.x); a.y = __float2half(v.y);
    b.x = __float2half(v.z); b.y = __float2half(v.w);
    reinterpret_cast<__half2*>(H)[i * 2 + 0] = a;
    reinterpret_cast<__half2*>(H)[i * 2 + 1] = b;
}

__global__ __launch_bounds__(256)
void bias2_kernel(const float* __restrict__ b1, const float* __restrict__ b2) {
    const int layer = blockIdx.x;
    const float* b = layer ? b2 : b1;
    const int t = threadIdx.x;
    float4 v = reinterpret_cast<const float4*>(b)[t];
    float w0 = v.x, w1 = v.y, w2 = v.z, w3 = v.w;
    float s = blockReduceSum(w0*w0 + w1*w1 + w2*w2 + w3*w3);
    float n = fmaxf(sqrtf(s), MIN_NORM);
    float sc = tanhf(n) / n;
    w0 *= sc; w1 *= sc; w2 *= sc; w3 *= sc;
    float s2 = blockReduceSum(w0*w0 + w1*w1 + w2*w2 + w3*w3);
    float n2 = fmaxf(sqrtf(s2), MIN_NORM);
    if (n2 > MAXNORM) { float f = MAXNORM / n2; w0*=f; w1*=f; w2*=f; w3*=f; }
    float s3 = blockReduceSum(w0*w0 + w1*w1 + w2*w2 + w3*w3);
    reinterpret_cast<float4*>(g_hb[layer])[t] = make_float4(w0, w1, w2, w3);
    if (t == 0) g_y2[layer] = s3;
}

__global__ __launch_bounds__(256)
void cvtx_kernel(const float* __restrict__ X, __half* __restrict__ H, float* __restrict__ xn) {
    const int t = threadIdx.x;
    const size_t base = (size_t)blockIdx.x * DIM;
    float4 v = reinterpret_cast<const float4*>(X + base)[t];
    float s = blockReduceSum(v.x * v.x + v.y * v.y + v.z * v.z + v.w * v.w);
    if (t == 0) xn[blockIdx.x] = fmaxf(sqrtf(s), MIN_NORM);
    __half2 a, b;
    a.x = __float2half(v.x); a.y = __float2half(v.y);
    b.x = __float2half(v.z); b.y = __float2half(v.w);
    reinterpret_cast<__half2*>(H + base)[t * 2 + 0] = a;
    reinterpret_cast<__half2*>(H + base)[t * 2 + 1] = b;
}

// ---------------- HMMA fp16 GEMM (R11 schedule + depth-2 B prefetch) ----------------
__global__ __launch_bounds__(256, 2)
void gemm1_kernel(const __half* __restrict__ A, const __half* __restrict__ B,
                  float* __restrict__ C) {
    extern __shared__ char smem[];
    const uint32_t s32 = smem_u32(smem);

    const int tid = threadIdx.x;
    const int wid = tid >> 5;
    const int lid = tid & 31;
    const int m0 = blockIdx.y * BM;
    const int n0 = blockIdx.x * BN;
    const int warpM = (wid & 3) * 32;
    const int warpN = (wid >> 2) * 64;

    // ---- loader mapping: thread handles chunks i and i+256 of each array ----
    const int row0 = tid >> 2;           // 0..63
    const int cc   = tid & 3;
    const uint32_t off0 = swz64(row0, cc);
    const uint32_t off1 = swz64(row0 + 64, cc);

    const __half* a0 = A + (size_t)(m0 + row0) * DIM + cc * 8;
    const __half* b0 = B + (size_t)(n0 + row0) * DIM + cc * 8;
    const size_t rstep = (size_t)64 * DIM;

    // ---- ldmatrix lane offsets ----
    uint32_t ofsA[2][2], ofsB[4][2];
    {
        const int lrow = (lid & 7) + ((lid >> 3) & 1) * 8;
        const int lchk = lid >> 4;       // 0/1
        #pragma unroll
        for (int mf = 0; mf < 2; ++mf)
            #pragma unroll
            for (int ks = 0; ks < 2; ++ks)
                ofsA[mf][ks] = swz64(warpM + mf * 16 + lrow, 2 * ks + lchk);
        #pragma unroll
        for (int p = 0; p < 4; ++p)
            #pragma unroll
            for (int ks = 0; ks < 2; ++ks)
                ofsB[p][ks] = swz64(warpN + p * 16 + lrow, 2 * ks + lchk);
    }

    float acc[2][8][4];
    #pragma unroll
    for (int i = 0; i < 2; ++i)
        #pragma unroll
        for (int j = 0; j < 8; ++j)
            #pragma unroll
            for (int q = 0; q < 4; ++q) acc[i][j][q] = 0.0f;

    auto issue = [&](int kt) {
        const uint32_t sb = s32 + (kt % STAGES) * STAGE_BYTES;
        const size_t ko = (size_t)kt * BKE;
        CP_ASYNC16(sb + ST_A + off0, a0 + ko);
        CP_ASYNC16(sb + ST_A + off1, a0 + rstep + ko);
        CP_ASYNC16(sb + ST_B + off0, b0 + ko);
        CP_ASYNC16(sb + ST_B + off1, b0 + rstep + ko);
    };

    // prologue: stages 0..2 in flight
    issue(0); CP_COMMIT();
    issue(1); CP_COMMIT();
    issue(2); CP_COMMIT();

    for (int kt = 0; kt < KITERS; ++kt) {
        // tail-exact wait: group kt must be fully complete before reading its stage.
        if (kt == KITERS - 1)      CP_WAIT0();
        else if (kt == KITERS - 2) CP_WAIT1();
        else                       CP_WAIT2();
        __syncthreads();

        const uint32_t sA = s32 + (kt % STAGES) * STAGE_BYTES;
        #pragma unroll
        for (int ks = 0; ks < 2; ++ks) {
            uint32_t ahf[2][4];
            ldsm4(ahf[0], sA + ST_A + ofsA[0][ks]);
            ldsm4(ahf[1], sA + ST_A + ofsA[1][ks]);
            // depth-2 B prefetch: 3-slot rotating buffer, consumer is ~8 MMAs behind
            uint32_t bb[3][4];
            ldsm4(bb[0], sA + ST_B + ofsB[0][ks]);
            ldsm4(bb[1], sA + ST_B + ofsB[1][ks]);
            #pragma unroll
            for (int p = 0; p < 4; ++p) {
                const uint32_t* bh = bb[p % 3];
                if (p < 2) ldsm4(bb[(p + 2) % 3], sA + ST_B + ofsB[p + 2][ks]);
                #pragma unroll
                for (int mf = 0; mf < 2; ++mf) {
                    mma16816(acc[mf][2*p],   ahf[mf], bh[0], bh[2]);
                    mma16816(acc[mf][2*p+1], ahf[mf], bh[1], bh[3]);
                }
            }
        }

        if (kt + 3 < KITERS) { issue(kt + 3); CP_COMMIT(); }
    }

    // ---- epilogue: direct stores ----
    #pragma unroll
    for (int mf = 0; mf < 2; ++mf) {
        #pragma unroll
        for (int nf = 0; nf < 8; ++nf) {
            const int r   = m0 + warpM + mf * 16 + (lid >> 2);
            const int col = n0 + warpN + nf * 8 + (lid & 3) * 2;
            float2 v0 = make_float2(acc[mf][nf][0], acc[mf][nf][1]);
            float2 v1 = make_float2(acc[mf][nf][2], acc[mf][nf][3]);
            *reinterpret_cast<float2*>(&C[(size_t)r * DIM + col])       = v0;
            *reinterpret_cast<float2*>(&C[(size_t)(r + 8) * DIM + col]) = v1;
        }
    }
}

// ---------------- fused per-row epilogue — analytic-norm version (R11-proven) ----------------
template<bool SPLIT>
__global__ __launch_bounds__(256)
void rowpost_kernel(const float* __restrict__ MX, const float* __restrict__ xnv,
                    float* __restrict__ OUT, __half* __restrict__ OH,
                    float* __restrict__ xnout, int layer) {
    const int t = threadIdx.x;
    const size_t base = (size_t)blockIdx.x * DIM;

    float4 v = reinterpret_cast<const float4*>(MX + base)[t];
    float w[4] = {v.x, v.y, v.z, v.w};
    const float xn = xnv[blockIdx.x];

    // gyro_matvec tail  (reduction #1)
    float r1 = blockReduceSum(w[0]*w[0] + w[1]*w[1] + w[2]*w[2] + w[3]*w[3]);
    const bool allzero = (r1 == 0.0f);
    const float mxn = fmaxf(sqrtf(r1), MIN_NORM);
    const float arg = (mxn / xn) * artanh_clip(xn);
    const float th  = tanhf(arg);
    float sres = allzero ? 0.0f : (th / mxn);
    #pragma unroll
    for (int i = 0; i < 4; ++i) w[i] *= sres;
    float ncur = allzero ? 0.0f : th;            // ||w|| in closed form

    // proj
    if (ncur > MAXNORM) {
        float f = MAXNORM / ncur;
        #pragma unroll
        for (int i = 0; i < 4; ++i) w[i] *= f;
        ncur = MAXNORM;
    }

    // gyro_add(hyp_bias): identity when bias is zero
    const float y2 = g_y2[layer];
    if (y2 != 0.0f) {
        float4 hv = reinterpret_cast<const float4*>(g_hb[layer])[t];
        float h[4] = {hv.x, hv.y, hv.z, hv.w};
        float x2 = blockReduceSum(w[0]*w[0] + w[1]*w[1] + w[2]*w[2] + w[3]*w[3]);
        float xy = blockReduceSum(w[0]*h[0] + w[1]*h[1] + w[2]*h[2] + w[3]*h[3]);
        float alpha = 1.0f + 2.0f * xy + y2;
        float beta  = 1.0f - x2;
        float inv   = 1.0f / fmaxf(1.0f + 2.0f * xy + x2 * y2, MIN_NORM);
        #pragma unroll
        for (int i = 0; i < 4; ++i) w[i] = (alpha * w[i] + beta * h[i]) * inv;
        float s = blockReduceSum(w[0]*w[0] + w[1]*w[1] + w[2]*w[2] + w[3]*w[3]);
        float n = fmaxf(sqrtf(s), MIN_NORM);
        if (n > MAXNORM) {
            float f = MAXNORM / n;
            #pragma unroll
            for (int i = 0; i < 4; ++i) w[i] *= f;
            n = MAXNORM;
        }
        ncur = n;
    }

    // logmap0 + tanh (norm known analytically)
    {
        float nl = fmaxf(ncur, MIN_NORM);
        float sl = artanh_clip(nl) / nl;
        #pragma unroll
        for (int i = 0; i < 4; ++i) w[i] = tanhf(sl * w[i]);
    }
    // expmap0  (reduction #2)
    {
        float s = blockReduceSum(w[0]*w[0] + w[1]*w[1] + w[2]*w[2] + w[3]*w[3]);
        float tn = fmaxf(sqrtf(s), MIN_NORM);
        float se = tanhf(tn) / tn;
        #pragma unroll
        for (int i = 0; i < 4; ++i) w[i] *= se;
        ncur = tanhf(tn);
    }
    // final proj
    float nfin = ncur;
    if (ncur > MAXNORM) {
        float f = MAXNORM / ncur;
        #pragma unroll
        for (int i = 0; i < 4; ++i) w[i] *= f;
        nfin = MAXNORM;
    }

    if (SPLIT) {
        __half2 a, b;
        a.x = __float2half(w[0]); a.y = __float2half(w[1]);
        b.x = __float2half(w[2]); b.y = __float2half(w[3]);
        reinterpret_cast<__half2*>(OH + base)[t * 2 + 0] = a;
        reinterpret_cast<__half2*>(OH + base)[t * 2 + 1] = b;
        if (t == 0) xnout[blockIdx.x] = fmaxf(nfin, MIN_NORM);
    } else {
        reinterpret_cast<float4*>(OUT + base)[t] = make_float4(w[0], w[1], w[2], w[3]);
    }
}

// ---------------- launch ----------------
extern "C" void kernel_launch(void* const* d_in, const int* in_sizes, int n_in,
                              void* d_out, int out_size) {
    const float* x  = (const float*)d_in[0];
    const float* W1 = (const float*)d_in[1];
    const float* b1 = (const float*)d_in[2];
    const float* W2 = (const float*)d_in[3];
    const float* b2 = (const float*)d_in[4];
    float* out = (float*)d_out;

    const int N = in_sizes[0] / DIM;

    float *mx = nullptr, *xn = nullptr;
    __half *a, *w1, *w2;
    cudaGetSymbolAddress((void**)&mx, g_mx);
    cudaGetSymbolAddress((void**)&xn, g_xn);
    cudaGetSymbolAddress((void**)&a,  g_a);
    cudaGetSymbolAddress((void**)&w1, g_w1);
    cudaGetSymbolAddress((void**)&w2, g_w2);

    cudaFuncSetAttribute(gemm1_kernel, cudaFuncAttributeMaxDynamicSharedMemorySize, SMEM_BYTES);

    const dim3 ggrid(DIM / BN, N / BM);   // (8, 256)
    const int wgrid = (DIM * DIM) / (4 * 256);   // 1024

    // merged prologue: 2 launches instead of 4
    cvtw2_kernel<<<2 * wgrid, 256>>>(W1, w1, W2, w2, wgrid);
    bias2_kernel<<<2, 256>>>(b1, b2);

    // layer 1
    cvtx_kernel<<<N, 256>>>(x, a, xn);
    gemm1_kernel<<<ggrid, 256, SMEM_BYTES>>>(a, w1, mx);
    rowpost_kernel<true><<<N, 256>>>(mx, xn, nullptr, a, xn, 0);

    // layer 2
    gemm1_kernel<<<ggrid, 256, SMEM_BYTES>>>(a, w2, out);
    rowpost_kernel<false><<<N, 256>>>(out, xn, out, nullptr, nullptr, 1);
}

// round 15
// speedup vs baseline: 1.0009x; 1.0009x over previous
#include <cuda_runtime.h>
#include <cuda_fp16.h>
#include <math.h>
#include <stdint.h>

#define DIM 1024
#define NMAX 32768
#define MAXNORM (1.0f - 1e-5f)
#define MIN_NORM 1e-15f

// ---------------- GEMM tiling (R7/R11/R13-proven config) ----------------
#define BM 128
#define BN 128
#define BKE 32                     // fp16 k elements per stage (64 bytes per row)
#define KITERS (DIM / BKE)         // 32
#define STAGES 4
// per-stage layout: A 8KB | B 8KB
#define ST_A 0
#define ST_B 8192
#define STAGE_BYTES 16384
#define SMEM_BYTES (STAGES * STAGE_BYTES)   // 64KB, 2 CTAs/SM

// ---------------- scratch (device globals) ----------------
__device__ __half  g_mxh[(size_t)NMAX * DIM];  // fp16 GEMM output
__device__ __half  g_a[(size_t)NMAX * DIM];    // activations fp16
__device__ __half  g_w1[DIM * DIM];
__device__ __half  g_w2[DIM * DIM];
__device__ float   g_xn[NMAX];
__device__ float   g_hb[2][DIM];
__device__ float   g_y2[2];

// ---------------- PTX helpers ----------------
__device__ __forceinline__ uint32_t smem_u32(const void* p) {
    uint32_t a;
    asm("{ .reg .u64 t; cvta.to.shared.u64 t, %1; cvt.u32.u64 %0, t; }" : "=r"(a) : "l"(p));
    return a;
}
#define CP_ASYNC16(dst, src) \
    asm volatile("cp.async.cg.shared.global [%0], [%1], 16;" :: "r"(dst), "l"(src) : "memory")
#define CP_COMMIT() asm volatile("cp.async.commit_group;" ::: "memory")
#define CP_WAIT2()  asm volatile("cp.async.wait_group 2;" ::: "memory")
#define CP_WAIT1()  asm volatile("cp.async.wait_group 1;" ::: "memory")
#define CP_WAIT0()  asm volatile("cp.async.wait_group 0;" ::: "memory")

__device__ __forceinline__ void ldsm4(uint32_t* r, uint32_t addr) {
    asm volatile("ldmatrix.sync.aligned.m8n8.x4.shared.b16 {%0,%1,%2,%3}, [%4];"
                 : "=r"(r[0]), "=r"(r[1]), "=r"(r[2]), "=r"(r[3]) : "r"(addr));
}
__device__ __forceinline__ void mma16816(float* c, const uint32_t* a, uint32_t b0, uint32_t b1) {
    asm volatile("mma.sync.aligned.m16n8k16.row.col.f32.f16.f16.f32 "
                 "{%0,%1,%2,%3}, {%4,%5,%6,%7}, {%8,%9}, {%0,%1,%2,%3};"
                 : "+f"(c[0]), "+f"(c[1]), "+f"(c[2]), "+f"(c[3])
                 : "r"(a[0]), "r"(a[1]), "r"(a[2]), "r"(a[3]), "r"(b0), "r"(b1));
}

// swizzled byte offset: 64B rows, 16B chunks, c in 0..3
__device__ __forceinline__ uint32_t swz64(int row, int c) {
    return (uint32_t)(row * 64 + ((c ^ ((row >> 1) & 3)) * 16));
}

// ---------------- generic helpers ----------------
__device__ __forceinline__ float artanh_clip(float x) {
    const float lim = 1.0f - 1e-7f;
    x = fminf(fmaxf(x, -lim), lim);
    return atanhf(x);
}
__device__ __forceinline__ float blockReduceSum(float v) {
    __shared__ float sbuf[32];
    #pragma unroll
    for (int o = 16; o > 0; o >>= 1) v += __shfl_xor_sync(0xffffffffu, v, o);
    const int lane = threadIdx.x & 31;
    const int w    = threadIdx.x >> 5;
    if (lane == 0) sbuf[w] = v;
    __syncthreads();
    if (w == 0) {
        float t = (lane < 8) ? sbuf[lane] : 0.0f;
        #pragma unroll
        for (int o = 4; o > 0; o >>= 1) t += __shfl_xor_sync(0xffffffffu, t, o);
        if (lane == 0) sbuf[0] = t;
    }
    __syncthreads();
    float r = sbuf[0];
    __syncthreads();
    return r;
}

// ---------------- small kernels (merged prologue) ----------------
__global__ __launch_bounds__(256)
void cvtw2_kernel(const float* __restrict__ W1, __half* __restrict__ H1,
                  const float* __restrict__ W2, __half* __restrict__ H2,
                  int nblk) {
    const bool second = (blockIdx.x >= nblk);
    const float* W = second ? W2 : W1;
    __half* H      = second ? H2 : H1;
    const size_t i = (size_t)(second ? blockIdx.x - nblk : blockIdx.x) * 256 + threadIdx.x;
    float4 v = reinterpret_cast<const float4*>(W)[i];
    __half2 a, b;
    a.x = __float2half(v.x); a.y = __float2half(v.y);
    b.x = __float2half(v.z); b.y = __float2half(v.w);
    reinterpret_cast<__half2*>(H)[i * 2 + 0] = a;
    reinterpret_cast<__half2*>(H)[i * 2 + 1] = b;
}

__global__ __launch_bounds__(256)
void bias2_kernel(const float* __restrict__ b1, const float* __restrict__ b2) {
    const int layer = blockIdx.x;
    const float* b = layer ? b2 : b1;
    const int t = threadIdx.x;
    float4 v = reinterpret_cast<const float4*>(b)[t];
    float w0 = v.x, w1 = v.y, w2 = v.z, w3 = v.w;
    float s = blockReduceSum(w0*w0 + w1*w1 + w2*w2 + w3*w3);
    float n = fmaxf(sqrtf(s), MIN_NORM);
    float sc = tanhf(n) / n;
    w0 *= sc; w1 *= sc; w2 *= sc; w3 *= sc;
    float s2 = blockReduceSum(w0*w0 + w1*w1 + w2*w2 + w3*w3);
    float n2 = fmaxf(sqrtf(s2), MIN_NORM);
    if (n2 > MAXNORM) { float f = MAXNORM / n2; w0*=f; w1*=f; w2*=f; w3*=f; }
    float s3 = blockReduceSum(w0*w0 + w1*w1 + w2*w2 + w3*w3);
    reinterpret_cast<float4*>(g_hb[layer])[t] = make_float4(w0, w1, w2, w3);
    if (t == 0) g_y2[layer] = s3;
}

__global__ __launch_bounds__(256)
void cvtx_kernel(const float* __restrict__ X, __half* __restrict__ H, float* __restrict__ xn) {
    const int t = threadIdx.x;
    const size_t base = (size_t)blockIdx.x * DIM;
    float4 v = reinterpret_cast<const float4*>(X + base)[t];
    float s = blockReduceSum(v.x * v.x + v.y * v.y + v.z * v.z + v.w * v.w);
    if (t == 0) xn[blockIdx.x] = fmaxf(sqrtf(s), MIN_NORM);
    __half2 a, b;
    a.x = __float2half(v.x); a.y = __float2half(v.y);
    b.x = __float2half(v.z); b.y = __float2half(v.w);
    reinterpret_cast<__half2*>(H + base)[t * 2 + 0] = a;
    reinterpret_cast<__half2*>(H + base)[t * 2 + 1] = b;
}

// ---------------- HMMA fp16 GEMM (R13 schedule, fp16 C output) ----------------
__global__ __launch_bounds__(256, 2)
void gemm1_kernel(const __half* __restrict__ A, const __half* __restrict__ B,
                  __half* __restrict__ C) {
    extern __shared__ char smem[];
    const uint32_t s32 = smem_u32(smem);

    const int tid = threadIdx.x;
    const int wid = tid >> 5;
    const int lid = tid & 31;
    const int m0 = blockIdx.y * BM;
    const int n0 = blockIdx.x * BN;
    const int warpM = (wid & 3) * 32;
    const int warpN = (wid >> 2) * 64;

    // ---- loader mapping: thread handles chunks i and i+256 of each array ----
    const int row0 = tid >> 2;           // 0..63
    const int cc   = tid & 3;
    const uint32_t off0 = swz64(row0, cc);
    const uint32_t off1 = swz64(row0 + 64, cc);

    const __half* a0 = A + (size_t)(m0 + row0) * DIM + cc * 8;
    const __half* b0 = B + (size_t)(n0 + row0) * DIM + cc * 8;
    const size_t rstep = (size_t)64 * DIM;

    // ---- ldmatrix lane offsets ----
    uint32_t ofsA[2][2], ofsB[4][2];
    {
        const int lrow = (lid & 7) + ((lid >> 3) & 1) * 8;
        const int lchk = lid >> 4;       // 0/1
        #pragma unroll
        for (int mf = 0; mf < 2; ++mf)
            #pragma unroll
            for (int ks = 0; ks < 2; ++ks)
                ofsA[mf][ks] = swz64(warpM + mf * 16 + lrow, 2 * ks + lchk);
        #pragma unroll
        for (int p = 0; p < 4; ++p)
            #pragma unroll
            for (int ks = 0; ks < 2; ++ks)
                ofsB[p][ks] = swz64(warpN + p * 16 + lrow, 2 * ks + lchk);
    }

    float acc[2][8][4];
    #pragma unroll
    for (int i = 0; i < 2; ++i)
        #pragma unroll
        for (int j = 0; j < 8; ++j)
            #pragma unroll
            for (int q = 0; q < 4; ++q) acc[i][j][q] = 0.0f;

    auto issue = [&](int kt) {
        const uint32_t sb = s32 + (kt % STAGES) * STAGE_BYTES;
        const size_t ko = (size_t)kt * BKE;
        CP_ASYNC16(sb + ST_A + off0, a0 + ko);
        CP_ASYNC16(sb + ST_A + off1, a0 + rstep + ko);
        CP_ASYNC16(sb + ST_B + off0, b0 + ko);
        CP_ASYNC16(sb + ST_B + off1, b0 + rstep + ko);
    };

    // prologue: stages 0..2 in flight
    issue(0); CP_COMMIT();
    issue(1); CP_COMMIT();
    issue(2); CP_COMMIT();

    for (int kt = 0; kt < KITERS; ++kt) {
        // tail-exact wait: group kt must be fully complete before reading its stage.
        if (kt == KITERS - 1)      CP_WAIT0();
        else if (kt == KITERS - 2) CP_WAIT1();
        else                       CP_WAIT2();
        __syncthreads();

        const uint32_t sA = s32 + (kt % STAGES) * STAGE_BYTES;
        #pragma unroll
        for (int ks = 0; ks < 2; ++ks) {
            uint32_t ahf[2][4];
            ldsm4(ahf[0], sA + ST_A + ofsA[0][ks]);
            ldsm4(ahf[1], sA + ST_A + ofsA[1][ks]);
            uint32_t bb[2][4];
            ldsm4(bb[0], sA + ST_B + ofsB[0][ks]);
            #pragma unroll
            for (int p = 0; p < 4; ++p) {
                const uint32_t* bh = bb[p & 1];
                if (p < 3) ldsm4(bb[(p + 1) & 1], sA + ST_B + ofsB[p + 1][ks]);
                #pragma unroll
                for (int mf = 0; mf < 2; ++mf) {
                    mma16816(acc[mf][2*p],   ahf[mf], bh[0], bh[2]);
                    mma16816(acc[mf][2*p+1], ahf[mf], bh[1], bh[3]);
                }
            }
        }

        if (kt + 3 < KITERS) { issue(kt + 3); CP_COMMIT(); }
    }

    // ---- epilogue: fp16 stores (half the traffic of fp32) ----
    #pragma unroll
    for (int mf = 0; mf < 2; ++mf) {
        #pragma unroll
        for (int nf = 0; nf < 8; ++nf) {
            const int r   = m0 + warpM + mf * 16 + (lid >> 2);
            const int col = n0 + warpN + nf * 8 + (lid & 3) * 2;
            __half2 v0 = __floats2half2_rn(acc[mf][nf][0], acc[mf][nf][1]);
            __half2 v1 = __floats2half2_rn(acc[mf][nf][2], acc[mf][nf][3]);
            *reinterpret_cast<__half2*>(&C[(size_t)r * DIM + col])       = v0;
            *reinterpret_cast<__half2*>(&C[(size_t)(r + 8) * DIM + col]) = v1;
        }
    }
}

// ---------------- fused per-row epilogue — analytic-norm, fp16 input ----------------
template<bool SPLIT>
__global__ __launch_bounds__(256)
void rowpost_kernel(const __half* __restrict__ MX, const float* __restrict__ xnv,
                    float* __restrict__ OUT, __half* __restrict__ OH,
                    float* __restrict__ xnout, int layer) {
    const int t = threadIdx.x;
    const size_t base = (size_t)blockIdx.x * DIM;

    // load 4 halves (8 bytes) per thread
    const __half2* mp = reinterpret_cast<const __half2*>(MX + base);
    __half2 h2a = mp[t * 2 + 0];
    __half2 h2b = mp[t * 2 + 1];
    float w[4];
    { float2 f0 = __half22float2(h2a); float2 f1 = __half22float2(h2b);
      w[0] = f0.x; w[1] = f0.y; w[2] = f1.x; w[3] = f1.y; }
    const float xn = xnv[blockIdx.x];

    // gyro_matvec tail  (reduction #1)
    float r1 = blockReduceSum(w[0]*w[0] + w[1]*w[1] + w[2]*w[2] + w[3]*w[3]);
    const bool allzero = (r1 == 0.0f);
    const float mxn = fmaxf(sqrtf(r1), MIN_NORM);
    const float arg = (mxn / xn) * artanh_clip(xn);
    const float th  = tanhf(arg);
    float sres = allzero ? 0.0f : (th / mxn);
    #pragma unroll
    for (int i = 0; i < 4; ++i) w[i] *= sres;
    float ncur = allzero ? 0.0f : th;            // ||w|| in closed form

    // proj
    if (ncur > MAXNORM) {
        float f = MAXNORM / ncur;
        #pragma unroll
        for (int i = 0; i < 4; ++i) w[i] *= f;
        ncur = MAXNORM;
    }

    // gyro_add(hyp_bias): identity when bias is zero
    const float y2 = g_y2[layer];
    if (y2 != 0.0f) {
        float4 hv = reinterpret_cast<const float4*>(g_hb[layer])[t];
        float h[4] = {hv.x, hv.y, hv.z, hv.w};
        float x2 = blockReduceSum(w[0]*w[0] + w[1]*w[1] + w[2]*w[2] + w[3]*w[3]);
        float xy = blockReduceSum(w[0]*h[0] + w[1]*h[1] + w[2]*h[2] + w[3]*h[3]);
        float alpha = 1.0f + 2.0f * xy + y2;
        float beta  = 1.0f - x2;
        float inv   = 1.0f / fmaxf(1.0f + 2.0f * xy + x2 * y2, MIN_NORM);
        #pragma unroll
        for (int i = 0; i < 4; ++i) w[i] = (alpha * w[i] + beta * h[i]) * inv;
        float s = blockReduceSum(w[0]*w[0] + w[1]*w[1] + w[2]*w[2] + w[3]*w[3]);
        float n = fmaxf(sqrtf(s), MIN_NORM);
        if (n > MAXNORM) {
            float f = MAXNORM / n;
            #pragma unroll
            for (int i = 0; i < 4; ++i) w[i] *= f;
            n = MAXNORM;
        }
        ncur = n;
    }

    // logmap0 + tanh (norm known analytically)
    {
        float nl = fmaxf(ncur, MIN_NORM);
        float sl = artanh_clip(nl) / nl;
        #pragma unroll
        for (int i = 0; i < 4; ++i) w[i] = tanhf(sl * w[i]);
    }
    // expmap0  (reduction #2)
    {
        float s = blockReduceSum(w[0]*w[0] + w[1]*w[1] + w[2]*w[2] + w[3]*w[3]);
        float tn = fmaxf(sqrtf(s), MIN_NORM);
        float se = tanhf(tn) / tn;
        #pragma unroll
        for (int i = 0; i < 4; ++i) w[i] *= se;
        ncur = tanhf(tn);
    }
    // final proj
    float nfin = ncur;
    if (ncur > MAXNORM) {
        float f = MAXNORM / ncur;
        #pragma unroll
        for (int i = 0; i < 4; ++i) w[i] *= f;
        nfin = MAXNORM;
    }

    if (SPLIT) {
        __half2 a, b;
        a.x = __float2half(w[0]); a.y = __float2half(w[1]);
        b.x = __float2half(w[2]); b.y = __float2half(w[3]);
        reinterpret_cast<__half2*>(OH + base)[t * 2 + 0] = a;
        reinterpret_cast<__half2*>(OH + base)[t * 2 + 1] = b;
        if (t == 0) xnout[blockIdx.x] = fmaxf(nfin, MIN_NORM);
    } else {
        reinterpret_cast<float4*>(OUT + base)[t] = make_float4(w[0], w[1], w[2], w[3]);
    }
}

// ---------------- launch ----------------
extern "C" void kernel_launch(void* const* d_in, const int* in_sizes, int n_in,
                              void* d_out, int out_size) {
    const float* x  = (const float*)d_in[0];
    const float* W1 = (const float*)d_in[1];
    const float* b1 = (const float*)d_in[2];
    const float* W2 = (const float*)d_in[3];
    const float* b2 = (const float*)d_in[4];
    float* out = (float*)d_out;

    const int N = in_sizes[0] / DIM;

    float *xn = nullptr;
    __half *mxh, *a, *w1, *w2;
    cudaGetSymbolAddress((void**)&mxh, g_mxh);
    cudaGetSymbolAddress((void**)&xn,  g_xn);
    cudaGetSymbolAddress((void**)&a,   g_a);
    cudaGetSymbolAddress((void**)&w1,  g_w1);
    cudaGetSymbolAddress((void**)&w2,  g_w2);

    cudaFuncSetAttribute(gemm1_kernel, cudaFuncAttributeMaxDynamicSharedMemorySize, SMEM_BYTES);

    const dim3 ggrid(DIM / BN, N / BM);   // (8, 256)
    const int wgrid = (DIM * DIM) / (4 * 256);   // 1024

    // merged prologue: 2 launches
    cvtw2_kernel<<<2 * wgrid, 256>>>(W1, w1, W2, w2, wgrid);
    bias2_kernel<<<2, 256>>>(b1, b2);

    // layer 1
    cvtx_kernel<<<N, 256>>>(x, a, xn);
    gemm1_kernel<<<ggrid, 256, SMEM_BYTES>>>(a, w1, mxh);
    rowpost_kernel<true><<<N, 256>>>(mxh, xn, nullptr, a, xn, 0);

    // layer 2
    gemm1_kernel<<<ggrid, 256, SMEM_BYTES>>>(a, w2, mxh);
    rowpost_kernel<false><<<N, 256>>>(mxh, xn, out, nullptr, nullptr, 1);
}

// round 16
// speedup vs baseline: 1.0189x; 1.0180x over previous
#include <cuda_runtime.h>
#include <cuda_fp16.h>
#include <math.h>
#include <stdint.h>

#define DIM 1024
#define NMAX 32768
#define MAXNORM (1.0f - 1e-5f)
#define MIN_NORM 1e-15f

// ---------------- GEMM tiling (R7/R11/R13-proven config) ----------------
#define BM 128
#define BN 128
#define BKE 32                     // fp16 k elements per stage (64 bytes per row)
#define KITERS (DIM / BKE)         // 32
#define STAGES 4
// per-stage layout: A 8KB | B 8KB
#define ST_A 0
#define ST_B 8192
#define STAGE_BYTES 16384
#define SMEM_BYTES (STAGES * STAGE_BYTES)   // 64KB, 2 CTAs/SM

// ---------------- scratch (device globals) ----------------
__device__ __half  g_mxh[(size_t)NMAX * DIM];  // fp16 GEMM output
__device__ __half  g_a[(size_t)NMAX * DIM];    // activations fp16
__device__ __half  g_w1[DIM * DIM];
__device__ __half  g_w2[DIM * DIM];
__device__ float   g_xn[NMAX];
__device__ float   g_hb[2][DIM];
__device__ float   g_y2[2];

// ---------------- PTX helpers ----------------
__device__ __forceinline__ uint32_t smem_u32(const void* p) {
    uint32_t a;
    asm("{ .reg .u64 t; cvta.to.shared.u64 t, %1; cvt.u32.u64 %0, t; }" : "=r"(a) : "l"(p));
    return a;
}
#define CP_ASYNC16(dst, src) \
    asm volatile("cp.async.cg.shared.global [%0], [%1], 16;" :: "r"(dst), "l"(src) : "memory")
#define CP_COMMIT() asm volatile("cp.async.commit_group;" ::: "memory")
#define CP_WAIT2()  asm volatile("cp.async.wait_group 2;" ::: "memory")
#define CP_WAIT1()  asm volatile("cp.async.wait_group 1;" ::: "memory")
#define CP_WAIT0()  asm volatile("cp.async.wait_group 0;" ::: "memory")

__device__ __forceinline__ void ldsm4(uint32_t* r, uint32_t addr) {
    asm volatile("ldmatrix.sync.aligned.m8n8.x4.shared.b16 {%0,%1,%2,%3}, [%4];"
                 : "=r"(r[0]), "=r"(r[1]), "=r"(r[2]), "=r"(r[3]) : "r"(addr));
}
__device__ __forceinline__ void mma16816(float* c, const uint32_t* a, uint32_t b0, uint32_t b1) {
    asm volatile("mma.sync.aligned.m16n8k16.row.col.f32.f16.f16.f32 "
                 "{%0,%1,%2,%3}, {%4,%5,%6,%7}, {%8,%9}, {%0,%1,%2,%3};"
                 : "+f"(c[0]), "+f"(c[1]), "+f"(c[2]), "+f"(c[3])
                 : "r"(a[0]), "r"(a[1]), "r"(a[2]), "r"(a[3]), "r"(b0), "r"(b1));
}

// swizzled byte offset: 64B rows, 16B chunks, c in 0..3
__device__ __forceinline__ uint32_t swz64(int row, int c) {
    return (uint32_t)(row * 64 + ((c ^ ((row >> 1) & 3)) * 16));
}

// ---------------- generic helpers ----------------
__device__ __forceinline__ float artanh_clip(float x) {
    const float lim = 1.0f - 1e-7f;
    x = fminf(fmaxf(x, -lim), lim);
    return atanhf(x);
}
// fast tanh via MUFU-based __expf: rel err ~5e-7, saturates cleanly (clamp kills inf/inf)
__device__ __forceinline__ float fast_tanh(float x) {
    x = fminf(fmaxf(x, -15.0f), 15.0f);
    float e = __expf(2.0f * x);
    return __fdividef(e - 1.0f, e + 1.0f);
}
__device__ __forceinline__ float blockReduceSum(float v) {
    __shared__ float sbuf[32];
    #pragma unroll
    for (int o = 16; o > 0; o >>= 1) v += __shfl_xor_sync(0xffffffffu, v, o);
    const int lane = threadIdx.x & 31;
    const int w    = threadIdx.x >> 5;
    if (lane == 0) sbuf[w] = v;
    __syncthreads();
    if (w == 0) {
        float t = (lane < 8) ? sbuf[lane] : 0.0f;
        #pragma unroll
        for (int o = 4; o > 0; o >>= 1) t += __shfl_xor_sync(0xffffffffu, t, o);
        if (lane == 0) sbuf[0] = t;
    }
    __syncthreads();
    float r = sbuf[0];
    __syncthreads();
    return r;
}

// ---------------- small kernels (merged prologue) ----------------
__global__ __launch_bounds__(256)
void cvtw2_kernel(const float* __restrict__ W1, __half* __restrict__ H1,
                  const float* __restrict__ W2, __half* __restrict__ H2,
                  int nblk) {
    const bool second = (blockIdx.x >= nblk);
    const float* W = second ? W2 : W1;
    __half* H      = second ? H2 : H1;
    const size_t i = (size_t)(second ? blockIdx.x - nblk : blockIdx.x) * 256 + threadIdx.x;
    float4 v = reinterpret_cast<const float4*>(W)[i];
    __half2 a, b;
    a.x = __float2half(v.x); a.y = __float2half(v.y);
    b.x = __float2half(v.z); b.y = __float2half(v.w);
    reinterpret_cast<__half2*>(H)[i * 2 + 0] = a;
    reinterpret_cast<__half2*>(H)[i * 2 + 1] = b;
}

__global__ __launch_bounds__(256)
void bias2_kernel(const float* __restrict__ b1, const float* __restrict__ b2) {
    const int layer = blockIdx.x;
    const float* b = layer ? b2 : b1;
    const int t = threadIdx.x;
    float4 v = reinterpret_cast<const float4*>(b)[t];
    float w0 = v.x, w1 = v.y, w2 = v.z, w3 = v.w;
    float s = blockReduceSum(w0*w0 + w1*w1 + w2*w2 + w3*w3);
    float n = fmaxf(sqrtf(s), MIN_NORM);
    float sc = tanhf(n) / n;
    w0 *= sc; w1 *= sc; w2 *= sc; w3 *= sc;
    float s2 = blockReduceSum(w0*w0 + w1*w1 + w2*w2 + w3*w3);
    float n2 = fmaxf(sqrtf(s2), MIN_NORM);
    if (n2 > MAXNORM) { float f = MAXNORM / n2; w0*=f; w1*=f; w2*=f; w3*=f; }
    float s3 = blockReduceSum(w0*w0 + w1*w1 + w2*w2 + w3*w3);
    reinterpret_cast<float4*>(g_hb[layer])[t] = make_float4(w0, w1, w2, w3);
    if (t == 0) g_y2[layer] = s3;
}

__global__ __launch_bounds__(256)
void cvtx_kernel(const float* __restrict__ X, __half* __restrict__ H, float* __restrict__ xn) {
    const int t = threadIdx.x;
    const size_t base = (size_t)blockIdx.x * DIM;
    float4 v = reinterpret_cast<const float4*>(X + base)[t];
    float s = blockReduceSum(v.x * v.x + v.y * v.y + v.z * v.z + v.w * v.w);
    if (t == 0) xn[blockIdx.x] = fmaxf(sqrtf(s), MIN_NORM);
    __half2 a, b;
    a.x = __float2half(v.x); a.y = __float2half(v.y);
    b.x = __float2half(v.z); b.y = __float2half(v.w);
    reinterpret_cast<__half2*>(H + base)[t * 2 + 0] = a;
    reinterpret_cast<__half2*>(H + base)[t * 2 + 1] = b;
}

// ---------------- HMMA fp16 GEMM (R13 schedule, fp16 C output) ----------------
__global__ __launch_bounds__(256, 2)
void gemm1_kernel(const __half* __restrict__ A, const __half* __restrict__ B,
                  __half* __restrict__ C) {
    extern __shared__ char smem[];
    const uint32_t s32 = smem_u32(smem);

    const int tid = threadIdx.x;
    const int wid = tid >> 5;
    const int lid = tid & 31;
    const int m0 = blockIdx.y * BM;
    const int n0 = blockIdx.x * BN;
    const int warpM = (wid & 3) * 32;
    const int warpN = (wid >> 2) * 64;

    const int row0 = tid >> 2;           // 0..63
    const int cc   = tid & 3;
    const uint32_t off0 = swz64(row0, cc);
    const uint32_t off1 = swz64(row0 + 64, cc);

    const __half* a0 = A + (size_t)(m0 + row0) * DIM + cc * 8;
    const __half* b0 = B + (size_t)(n0 + row0) * DIM + cc * 8;
    const size_t rstep = (size_t)64 * DIM;

    uint32_t ofsA[2][2], ofsB[4][2];
    {
        const int lrow = (lid & 7) + ((lid >> 3) & 1) * 8;
        const int lchk = lid >> 4;       // 0/1
        #pragma unroll
        for (int mf = 0; mf < 2; ++mf)
            #pragma unroll
            for (int ks = 0; ks < 2; ++ks)
                ofsA[mf][ks] = swz64(warpM + mf * 16 + lrow, 2 * ks + lchk);
        #pragma unroll
        for (int p = 0; p < 4; ++p)
            #pragma unroll
            for (int ks = 0; ks < 2; ++ks)
                ofsB[p][ks] = swz64(warpN + p * 16 + lrow, 2 * ks + lchk);
    }

    float acc[2][8][4];
    #pragma unroll
    for (int i = 0; i < 2; ++i)
        #pragma unroll
        for (int j = 0; j < 8; ++j)
            #pragma unroll
            for (int q = 0; q < 4; ++q) acc[i][j][q] = 0.0f;

    auto issue = [&](int kt) {
        const uint32_t sb = s32 + (kt % STAGES) * STAGE_BYTES;
        const size_t ko = (size_t)kt * BKE;
        CP_ASYNC16(sb + ST_A + off0, a0 + ko);
        CP_ASYNC16(sb + ST_A + off1, a0 + rstep + ko);
        CP_ASYNC16(sb + ST_B + off0, b0 + ko);
        CP_ASYNC16(sb + ST_B + off1, b0 + rstep + ko);
    };

    issue(0); CP_COMMIT();
    issue(1); CP_COMMIT();
    issue(2); CP_COMMIT();

    for (int kt = 0; kt < KITERS; ++kt) {
        if (kt == KITERS - 1)      CP_WAIT0();
        else if (kt == KITERS - 2) CP_WAIT1();
        else                       CP_WAIT2();
        __syncthreads();

        const uint32_t sA = s32 + (kt % STAGES) * STAGE_BYTES;
        #pragma unroll
        for (int ks = 0; ks < 2; ++ks) {
            uint32_t ahf[2][4];
            ldsm4(ahf[0], sA + ST_A + ofsA[0][ks]);
            ldsm4(ahf[1], sA + ST_A + ofsA[1][ks]);
            uint32_t bb[2][4];
            ldsm4(bb[0], sA + ST_B + ofsB[0][ks]);
            #pragma unroll
            for (int p = 0; p < 4; ++p) {
                const uint32_t* bh = bb[p & 1];
                if (p < 3) ldsm4(bb[(p + 1) & 1], sA + ST_B + ofsB[p + 1][ks]);
                #pragma unroll
                for (int mf = 0; mf < 2; ++mf) {
                    mma16816(acc[mf][2*p],   ahf[mf], bh[0], bh[2]);
                    mma16816(acc[mf][2*p+1], ahf[mf], bh[1], bh[3]);
                }
            }
        }

        if (kt + 3 < KITERS) { issue(kt + 3); CP_COMMIT(); }
    }

    // fp16 stores
    #pragma unroll
    for (int mf = 0; mf < 2; ++mf) {
        #pragma unroll
        for (int nf = 0; nf < 8; ++nf) {
            const int r   = m0 + warpM + mf * 16 + (lid >> 2);
            const int col = n0 + warpN + nf * 8 + (lid & 3) * 2;
            __half2 v0 = __floats2half2_rn(acc[mf][nf][0], acc[mf][nf][1]);
            __half2 v1 = __floats2half2_rn(acc[mf][nf][2], acc[mf][nf][3]);
            *reinterpret_cast<__half2*>(&C[(size_t)r * DIM + col])       = v0;
            *reinterpret_cast<__half2*>(&C[(size_t)(r + 8) * DIM + col]) = v1;
        }
    }
}

// ---------------- fused per-row epilogue — analytic-norm + fast tanh ----------------
template<bool SPLIT>
__global__ __launch_bounds__(256)
void rowpost_kernel(const __half* __restrict__ MX, const float* __restrict__ xnv,
                    float* __restrict__ OUT, __half* __restrict__ OH,
                    float* __restrict__ xnout, int layer) {
    const int t = threadIdx.x;
    const size_t base = (size_t)blockIdx.x * DIM;

    const __half2* mp = reinterpret_cast<const __half2*>(MX + base);
    __half2 h2a = mp[t * 2 + 0];
    __half2 h2b = mp[t * 2 + 1];
    float w[4];
    { float2 f0 = __half22float2(h2a); float2 f1 = __half22float2(h2b);
      w[0] = f0.x; w[1] = f0.y; w[2] = f1.x; w[3] = f1.y; }
    const float xn = xnv[blockIdx.x];

    // gyro_matvec tail  (reduction #1)
    float r1 = blockReduceSum(w[0]*w[0] + w[1]*w[1] + w[2]*w[2] + w[3]*w[3]);
    const bool allzero = (r1 == 0.0f);
    const float mxn = fmaxf(sqrtf(r1), MIN_NORM);
    const float arg = (mxn / xn) * artanh_clip(xn);
    const float th  = fast_tanh(arg);
    float sres = allzero ? 0.0f : (th / mxn);
    #pragma unroll
    for (int i = 0; i < 4; ++i) w[i] *= sres;
    float ncur = allzero ? 0.0f : th;            // ||w|| in closed form

    // proj
    if (ncur > MAXNORM) {
        float f = MAXNORM / ncur;
        #pragma unroll
        for (int i = 0; i < 4; ++i) w[i] *= f;
        ncur = MAXNORM;
    }

    // gyro_add(hyp_bias): identity when bias is zero
    const float y2 = g_y2[layer];
    if (y2 != 0.0f) {
        float4 hv = reinterpret_cast<const float4*>(g_hb[layer])[t];
        float h[4] = {hv.x, hv.y, hv.z, hv.w};
        float x2 = blockReduceSum(w[0]*w[0] + w[1]*w[1] + w[2]*w[2] + w[3]*w[3]);
        float xy = blockReduceSum(w[0]*h[0] + w[1]*h[1] + w[2]*h[2] + w[3]*h[3]);
        float alpha = 1.0f + 2.0f * xy + y2;
        float beta  = 1.0f - x2;
        float inv   = 1.0f / fmaxf(1.0f + 2.0f * xy + x2 * y2, MIN_NORM);
        #pragma unroll
        for (int i = 0; i < 4; ++i) w[i] = (alpha * w[i] + beta * h[i]) * inv;
        float s = blockReduceSum(w[0]*w[0] + w[1]*w[1] + w[2]*w[2] + w[3]*w[3]);
        float n = fmaxf(sqrtf(s), MIN_NORM);
        if (n > MAXNORM) {
            float f = MAXNORM / n;
            #pragma unroll
            for (int i = 0; i < 4; ++i) w[i] *= f;
            n = MAXNORM;
        }
        ncur = n;
    }

    // logmap0 + elementwise fast tanh (the hot path: 4 per thread)
    {
        float nl = fmaxf(ncur, MIN_NORM);
        float sl = artanh_clip(nl) / nl;
        #pragma unroll
        for (int i = 0; i < 4; ++i) w[i] = fast_tanh(sl * w[i]);
    }
    // expmap0  (reduction #2)
    {
        float s = blockReduceSum(w[0]*w[0] + w[1]*w[1] + w[2]*w[2] + w[3]*w[3]);
        float tn = fmaxf(sqrtf(s), MIN_NORM);
        float tt = fast_tanh(tn);
        float se = tt / tn;
        #pragma unroll
        for (int i = 0; i < 4; ++i) w[i] *= se;
        ncur = tt;
    }
    // final proj
    float nfin = ncur;
    if (ncur > MAXNORM) {
        float f = MAXNORM / ncur;
        #pragma unroll
        for (int i = 0; i < 4; ++i) w[i] *= f;
        nfin = MAXNORM;
    }

    if (SPLIT) {
        __half2 a, b;
        a.x = __float2half(w[0]); a.y = __float2half(w[1]);
        b.x = __float2half(w[2]); b.y = __float2half(w[3]);
        reinterpret_cast<__half2*>(OH + base)[t * 2 + 0] = a;
        reinterpret_cast<__half2*>(OH + base)[t * 2 + 1] = b;
        if (t == 0) xnout[blockIdx.x] = fmaxf(nfin, MIN_NORM);
    } else {
        reinterpret_cast<float4*>(OUT + base)[t] = make_float4(w[0], w[1], w[2], w[3]);
    }
}

// ---------------- launch ----------------
extern "C" void kernel_launch(void* const* d_in, const int* in_sizes, int n_in,
                              void* d_out, int out_size) {
    const float* x  = (const float*)d_in[0];
    const float* W1 = (const float*)d_in[1];
    const float* b1 = (const float*)d_in[2];
    const float* W2 = (const float*)d_in[3];
    const float* b2 = (const float*)d_in[4];
    float* out = (float*)d_out;

    const int N = in_sizes[0] / DIM;

    float *xn = nullptr;
    __half *mxh, *a, *w1, *w2;
    cudaGetSymbolAddress((void**)&mxh, g_mxh);
    cudaGetSymbolAddress((void**)&xn,  g_xn);
    cudaGetSymbolAddress((void**)&a,   g_a);
    cudaGetSymbolAddress((void**)&w1,  g_w1);
    cudaGetSymbolAddress((void**)&w2,  g_w2);

    cudaFuncSetAttribute(gemm1_kernel, cudaFuncAttributeMaxDynamicSharedMemorySize, SMEM_BYTES);

    const dim3 ggrid(DIM / BN, N / BM);   // (8, 256)
    const int wgrid = (DIM * DIM) / (4 * 256);   // 1024

    cvtw2_kernel<<<2 * wgrid, 256>>>(W1, w1, W2, w2, wgrid);
    bias2_kernel<<<2, 256>>>(b1, b2);

    // layer 1
    cvtx_kernel<<<N, 256>>>(x, a, xn);
    gemm1_kernel<<<ggrid, 256, SMEM_BYTES>>>(a, w1, mxh);
    rowpost_kernel<true><<<N, 256>>>(mxh, xn, nullptr, a, xn, 0);

    // layer 2
    gemm1_kernel<<<ggrid, 256, SMEM_BYTES>>>(a, w2, mxh);
    rowpost_kernel<false><<<N, 256>>>(mxh, xn, out, nullptr, nullptr, 1);
}